// round 8
// baseline (speedup 1.0000x reference)
#include <cuda_runtime.h>
#include <cuda_bf16.h>
#include <math_constants.h>

#define Bsz 1024
#define Ssz 128
#define NW (Bsz*Ssz)   // 131072 words

typedef unsigned long long u64;

__device__ __forceinline__ float tanh_fast(float x){ float y; asm("tanh.approx.f32 %0, %1;" : "=f"(y) : "f"(x)); return y; }
__device__ __forceinline__ u64 pk(float lo, float hi){ u64 r; asm("mov.b64 %0, {%1,%2};" : "=l"(r) : "f"(lo), "f"(hi)); return r; }
__device__ __forceinline__ void upk(u64 v, float& lo, float& hi){ asm("mov.b64 {%0,%1}, %2;" : "=f"(lo), "=f"(hi) : "l"(v)); }
__device__ __forceinline__ u64 ffma2(u64 a, u64 b, u64 c){ u64 d; asm("fma.rn.f32x2 %0, %1, %2, %3;" : "=l"(d) : "l"(a), "l"(b), "l"(c)); return d; }
__device__ __forceinline__ u64 fmul2(u64 a, u64 b){ u64 d; asm("mul.rn.f32x2 %0, %1, %2;" : "=l"(d) : "l"(a), "l"(b)); return d; }

// ============ fully fused: one block per sentence, 128 threads ============
__global__ __launch_bounds__(128,6) void fused_tagger(
    const int* __restrict__ word_idx, const int* __restrict__ char_idx,
    const float* __restrict__ word_emb, const float* __restrict__ char_emb,
    const float* __restrict__ Wc, const float* __restrict__ bc,
    const float* __restrict__ Wih_f, const float* __restrict__ b_f,
    const float* __restrict__ Wih_b, const float* __restrict__ b_b,
    const float* __restrict__ Whh_f, const float* __restrict__ Whh_b,
    const float* __restrict__ Wt, const float* __restrict__ bt,
    float* __restrict__ out)
{
    // aliased region: tables (Phase A) / sH (Phase B/C)
    __shared__ __align__(16) char uraw[8064];
    float4* sP = (float4*)uraw;                    // 300 entries (4800 B)
    float4* sW = (float4*)(uraw + 4800);           // 192 entries (3072 B)
    float*  sB = (float*)(uraw + 4800 + 3072);     // 48 floats
    float*  sH = (float*)uraw;                     // [128 steps][12] (after Phase A)

    __shared__ float sXG[Ssz*49];  // [word][49]: gates 0..23 fwd, 24..47 bwd, 1 pad

    const unsigned FULL = 0xffffffffu;
    int tid  = threadIdx.x;
    int lane = tid & 31;
    int warp = tid >> 5;
    int blk  = blockIdx.x;         // sentence

    // ---- hoist per-word global loads (latency overlaps table build) ----
    size_t w = (size_t)blk*Ssz + tid;
    int ci[14];
    const int2* cp = (const int2*)(char_idx + w*14);
    #pragma unroll
    for (int k=0;k<7;k++){ int2 v = __ldg(cp+k); ci[2*k]=v.x; ci[2*k+1]=v.y; }

    float x[14];
    int widx = __ldg(word_idx + w);
    const float2* wep = (const float2*)(word_emb) + (size_t)widx*5;
    #pragma unroll
    for (int k=0;k<5;k++){ float2 v = __ldg(wep+k); x[2*k]=v.x; x[2*k+1]=v.y; }

    // ---- build tables ----
    for (int i = tid; i < 300; i += 128){
        int c = i/3, k = i%3;
        float4 acc;
        if (k==0){ acc.x=__ldg(bc+0); acc.y=__ldg(bc+1); acc.z=__ldg(bc+2); acc.w=__ldg(bc+3); }
        else     { acc.x=0.f; acc.y=0.f; acc.z=0.f; acc.w=0.f; }
        #pragma unroll
        for (int m=0;m<6;m++){
            float e = __ldg(char_emb + c*6 + m);
            acc.x = fmaf(e, __ldg(Wc + 0*18 + k*6 + m), acc.x);
            acc.y = fmaf(e, __ldg(Wc + 1*18 + k*6 + m), acc.y);
            acc.z = fmaf(e, __ldg(Wc + 2*18 + k*6 + m), acc.z);
            acc.w = fmaf(e, __ldg(Wc + 3*18 + k*6 + m), acc.w);
        }
        sP[i] = acc;
    }
    for (int i = tid; i < 192; i += 128){
        int g = i >> 2, q = i & 3;
        const float* Wih = (g < 24) ? (Wih_f + g*14) : (Wih_b + (g-24)*14);
        int base = q*4;
        float4 wv;
        wv.x = (base+0 < 14) ? __ldg(Wih+base+0) : 0.f;
        wv.y = (base+1 < 14) ? __ldg(Wih+base+1) : 0.f;
        wv.z = (base+2 < 14) ? __ldg(Wih+base+2) : 0.f;
        wv.w = (base+3 < 14) ? __ldg(Wih+base+3) : 0.f;
        sW[i] = wv;
    }
    if (tid < 48) sB[tid] = (tid < 24) ? __ldg(b_f + tid) : __ldg(b_b + tid - 24);
    __syncthreads();

    // ---- Phase A: conv + maxpool ----
    float4 a = make_float4(-CUDART_INF_F,-CUDART_INF_F,-CUDART_INF_F,-CUDART_INF_F);
    #pragma unroll
    for (int win=0; win<12; win++){
        float4 s0 = sP[ci[win]  *3 + 0];
        float4 s1 = sP[ci[win+1]*3 + 1];
        float4 s2 = sP[ci[win+2]*3 + 2];
        a.x = fmaxf(a.x, s0.x + s1.x + s2.x);
        a.y = fmaxf(a.y, s0.y + s1.y + s2.y);
        a.z = fmaxf(a.z, s0.z + s1.z + s2.z);
        a.w = fmaxf(a.w, s0.w + s1.w + s2.w);
    }

    // ---- 48 gate pre-activations, packed FFMA2 (x as 8 f32x2, pad with 0) ----
    {
        u64 xp[8];
        #pragma unroll
        for (int q=0;q<5;q++) xp[q] = pk(x[2*q], x[2*q+1]);
        xp[5] = pk(a.x, a.y); xp[6] = pk(a.z, a.w); xp[7] = pk(0.f, 0.f);

        const ulonglong2* sW2 = (const ulonglong2*)sW;  // [g*4+q] = {w(4q,4q+1), w(4q+2,4q+3)}
        float* st = &sXG[tid*49];    // stride 49 (odd): conflict-free
        #pragma unroll
        for (int g=0; g<48; g++){
            ulonglong2 w0 = sW2[g*4+0], w1 = sW2[g*4+1], w2 = sW2[g*4+2], w3 = sW2[g*4+3];
            u64 acc = fmul2(xp[0], w0.x);
            acc = ffma2(xp[1], w0.y, acc);
            acc = ffma2(xp[2], w1.x, acc);
            acc = ffma2(xp[3], w1.y, acc);
            acc = ffma2(xp[4], w2.x, acc);
            acc = ffma2(xp[5], w2.y, acc);
            acc = ffma2(xp[6], w3.x, acc);
            float lo, hi; upk(acc, lo, hi);
            st[g] = (lo + hi) + sB[g];
        }
    }

    // ---- Phase C weight pre-load (packed along k) BEFORE Phase B: latency hidden ----
    u64 wp[5][6]; float bs[5];
    #pragma unroll
    for (int t5=0; t5<5; t5++){
        int j = lane + 32*t5;
        bool valid = (j < 135);
        bs[t5] = valid ? __ldg(bt + j) : -1e30f;   // exp(-1e30)=0, drops out of sum
        #pragma unroll
        for (int kq=0; kq<6; kq++){
            float wl = valid ? __ldg(Wt + j*12 + 2*kq)   : 0.f;
            float wh = valid ? __ldg(Wt + j*12 + 2*kq+1) : 0.f;
            wp[t5][kq] = pk(wl, wh);
        }
    }
    __syncthreads();   // tables dead below; sH aliases them

    // ---- Phase B: warps 0/1 run fwd/bwd; lane j<24 owns gate j (i,f,g,o) ----
    if (warp < 2){
        int d   = warp;
        int jc  = (lane < 24) ? lane : 0;
        bool is_g = (lane >= 12 && lane < 18);
        float sm = is_g ? 1.f : 0.5f;     // sigmoid(x) = 0.5*tanh(0.5x)+0.5
        float ab = is_g ? 0.f : 0.5f;

        const float* Whh = d ? Whh_b : Whh_f;
        float w0=__ldg(Whh+jc*6+0), w1=__ldg(Whh+jc*6+1), w2=__ldg(Whh+jc*6+2),
              w3=__ldg(Whh+jc*6+3), w4=__ldg(Whh+jc*6+4), w5=__ldg(Whh+jc*6+5);

        const float* xgp = &sXG[d*24];
        float h0=0.f,h1=0.f,h2=0.f,h3=0.f,h4=0.f,h5=0.f,c=0.f;
        int s  = d ? (Ssz-1) : 0;
        int ds = d ? -1 : 1;

        float pf = xgp[s*49 + jc];
        #pragma unroll 4
        for (int t=0; t<Ssz; t++){
            float gcur = pf;
            if (t+1 < Ssz) pf = xgp[(s+ds)*49 + jc];   // one-ahead smem prefetch

            float g = fmaf(w0,h0,gcur);
            g = fmaf(w1,h1,g); g = fmaf(w2,h2,g); g = fmaf(w3,h3,g);
            g = fmaf(w4,h4,g); g = fmaf(w5,h5,g);
            float act = fmaf(sm, tanh_fast(g*sm), ab);

            float af = __shfl_sync(FULL, act, lane+6);
            float ag = __shfl_sync(FULL, act, lane+12);
            float ao = __shfl_sync(FULL, act, lane+18);
            c = fmaf(af, c, act*ag);
            float hj = ao * tanh_fast(c);

            h0=__shfl_sync(FULL,hj,0); h1=__shfl_sync(FULL,hj,1); h2=__shfl_sync(FULL,hj,2);
            h3=__shfl_sync(FULL,hj,3); h4=__shfl_sync(FULL,hj,4); h5=__shfl_sync(FULL,hj,5);

            if (lane < 6) sH[s*12 + d*6 + lane] = hj;
            s += ds;
        }
    }
    __syncthreads();

    // ---- Phase C: tag linear + log_softmax, packed FFMA2, weights in registers ----
    int base = warp*32;
    for (int it=0; it<32; it++){
        int p = base + it;
        const u64* hp = (const u64*)(sH + p*12);   // 48B stride -> 8B aligned, LDS.64 broadcast
        u64 hq[6];
        #pragma unroll
        for (int q=0;q<6;q++) hq[q] = hp[q];

        // |v| bounded (|h|<1, small weights): safe to skip max-shift
        float tg[5]; float zs = 0.f;
        #pragma unroll
        for (int t5=0; t5<5; t5++){
            u64 acc = fmul2(hq[0], wp[t5][0]);
            acc = ffma2(hq[1], wp[t5][1], acc);
            acc = ffma2(hq[2], wp[t5][2], acc);
            acc = ffma2(hq[3], wp[t5][3], acc);
            acc = ffma2(hq[4], wp[t5][4], acc);
            acc = ffma2(hq[5], wp[t5][5], acc);
            float lo, hi; upk(acc, lo, hi);
            float v = (lo + hi) + bs[t5];
            tg[t5] = v;
            zs += __expf(v);
        }
        #pragma unroll
        for (int o=16;o>0;o>>=1) zs += __shfl_xor_sync(FULL, zs, o);
        float lse = __logf(zs);

        float* op = out + ((size_t)blk*Ssz + p)*135;
        #pragma unroll
        for (int t5=0; t5<5; t5++){
            int j = lane + 32*t5;
            if (j < 135) op[j] = tg[t5] - lse;
        }
    }
}

// ---------------- Launch ----------------
extern "C" void kernel_launch(void* const* d_in, const int* in_sizes, int n_in,
                              void* d_out, int out_size)
{
    const int *word_idx=nullptr,*char_idx=nullptr;
    const float *word_emb=nullptr,*char_emb=nullptr,*Wc=nullptr,*bc=nullptr,
        *Wih_f=nullptr,*Whh_f=nullptr,*b_f=nullptr,
        *Wih_b=nullptr,*Whh_b=nullptr,*b_b=nullptr,*Wt=nullptr,*bt=nullptr;
    for (int i=0;i<n_in;i++){
        int sz = in_sizes[i]; const void* p = d_in[i];
        switch (sz){
            case 131072:  word_idx=(const int*)p; break;          // [B,S]
            case 1835008: char_idx=(const int*)p; break;          // [B,S,LP]
            case 500000:  word_emb=(const float*)p; break;        // [V,WE]
            case 600:     char_emb=(const float*)p; break;        // [A,CE]
            case 72:      Wc=(const float*)p; break;              // [Lf,K*CE]
            case 4:       bc=(const float*)p; break;              // [Lf]
            case 336:     if(!Wih_f) Wih_f=(const float*)p; else Wih_b=(const float*)p; break;
            case 144:     if(!Whh_f) Whh_f=(const float*)p; else Whh_b=(const float*)p; break;
            case 24:      if(!b_f)   b_f  =(const float*)p; else b_b  =(const float*)p; break;
            case 1620:    Wt=(const float*)p; break;              // [T,2H]
            case 135:     bt=(const float*)p; break;              // [T]
        }
    }

    fused_tagger<<<Bsz, 128>>>(word_idx, char_idx, word_emb, char_emb,
                               Wc, bc, Wih_f, b_f, Wih_b, b_b,
                               Whh_f, Whh_b, Wt, bt, (float*)d_out);
    (void)out_size; (void)n_in;
}

// round 9
// speedup vs baseline: 1.4023x; 1.4023x over previous
#include <cuda_runtime.h>
#include <cuda_bf16.h>
#include <math_constants.h>

#define Bsz 1024
#define Ssz 128
#define NW (Bsz*Ssz)   // 131072 words

__device__ __forceinline__ float tanh_fast(float x){ float y; asm("tanh.approx.f32 %0, %1;" : "=f"(y) : "f"(x)); return y; }

// ============ fully fused: one block per sentence, 128 threads ============
// Phase A: 128 threads, 1 word each: char-CNN + emb + 48 xgate pre-acts -> sXG
// Phase B: warps 0/1 = fwd/bwd LSTM from sXG -> sH (aliases dead tables);
//          warps 2/3 preload Phase-C weights meanwhile.
// Phase C: 4 warps x 32 pairs: tag linear + log_softmax -> out
__global__ __launch_bounds__(128,6) void fused_tagger(
    const int* __restrict__ word_idx, const int* __restrict__ char_idx,
    const float* __restrict__ word_emb, const float* __restrict__ char_emb,
    const float* __restrict__ Wc, const float* __restrict__ bc,
    const float* __restrict__ Wih_f, const float* __restrict__ b_f,
    const float* __restrict__ Wih_b, const float* __restrict__ b_b,
    const float* __restrict__ Whh_f, const float* __restrict__ Whh_b,
    const float* __restrict__ Wt, const float* __restrict__ bt,
    float* __restrict__ out)
{
    // aliased region: tables (Phase A) / sH (Phase B/C)
    __shared__ __align__(16) char uraw[8064];
    float4* sP = (float4*)uraw;                    // 300 entries (4800 B)
    float4* sW = (float4*)(uraw + 4800);           // 192 entries (3072 B)
    float*  sB = (float*)(uraw + 4800 + 3072);     // 48 floats
    float*  sH = (float*)uraw;                     // [128 steps][12] (after Phase A)

    __shared__ float sXG[Ssz*49];  // [word][49]: gates 0..23 fwd, 24..47 bwd, 1 pad

    const unsigned FULL = 0xffffffffu;
    int tid  = threadIdx.x;
    int lane = tid & 31;
    int warp = tid >> 5;
    int blk  = blockIdx.x;         // sentence

    // ---- hoist per-word global loads (latency overlaps table build) ----
    size_t w = (size_t)blk*Ssz + tid;
    int ci[14];
    const int2* cp = (const int2*)(char_idx + w*14);
    #pragma unroll
    for (int k=0;k<7;k++){ int2 v = __ldg(cp+k); ci[2*k]=v.x; ci[2*k+1]=v.y; }

    float x[16];
    int widx = __ldg(word_idx + w);
    const float2* wep = (const float2*)(word_emb) + (size_t)widx*5;
    #pragma unroll
    for (int k=0;k<5;k++){ float2 v = __ldg(wep+k); x[2*k]=v.x; x[2*k+1]=v.y; }
    x[14]=0.f; x[15]=0.f;

    // ---- build tables ----
    for (int i = tid; i < 300; i += 128){
        int c = i/3, k = i%3;
        float4 acc;
        if (k==0){ acc.x=__ldg(bc+0); acc.y=__ldg(bc+1); acc.z=__ldg(bc+2); acc.w=__ldg(bc+3); }
        else     { acc.x=0.f; acc.y=0.f; acc.z=0.f; acc.w=0.f; }
        #pragma unroll
        for (int m=0;m<6;m++){
            float e = __ldg(char_emb + c*6 + m);
            acc.x = fmaf(e, __ldg(Wc + 0*18 + k*6 + m), acc.x);
            acc.y = fmaf(e, __ldg(Wc + 1*18 + k*6 + m), acc.y);
            acc.z = fmaf(e, __ldg(Wc + 2*18 + k*6 + m), acc.z);
            acc.w = fmaf(e, __ldg(Wc + 3*18 + k*6 + m), acc.w);
        }
        sP[i] = acc;
    }
    for (int i = tid; i < 192; i += 128){
        int g = i >> 2, q = i & 3;
        const float* Wih = (g < 24) ? (Wih_f + g*14) : (Wih_b + (g-24)*14);
        int base = q*4;
        float4 wv;
        wv.x = (base+0 < 14) ? __ldg(Wih+base+0) : 0.f;
        wv.y = (base+1 < 14) ? __ldg(Wih+base+1) : 0.f;
        wv.z = (base+2 < 14) ? __ldg(Wih+base+2) : 0.f;
        wv.w = (base+3 < 14) ? __ldg(Wih+base+3) : 0.f;
        sW[i] = wv;
    }
    if (tid < 48) sB[tid] = (tid < 24) ? __ldg(b_f + tid) : __ldg(b_b + tid - 24);
    __syncthreads();

    // ---- Phase A: conv + maxpool ----
    float4 a = make_float4(-CUDART_INF_F,-CUDART_INF_F,-CUDART_INF_F,-CUDART_INF_F);
    #pragma unroll
    for (int win=0; win<12; win++){
        float4 s0 = sP[ci[win]  *3 + 0];
        float4 s1 = sP[ci[win+1]*3 + 1];
        float4 s2 = sP[ci[win+2]*3 + 2];
        a.x = fmaxf(a.x, s0.x + s1.x + s2.x);
        a.y = fmaxf(a.y, s0.y + s1.y + s2.y);
        a.z = fmaxf(a.z, s0.z + s1.z + s2.z);
        a.w = fmaxf(a.w, s0.w + s1.w + s2.w);
    }
    x[10]=a.x; x[11]=a.y; x[12]=a.z; x[13]=a.w;

    // ---- 48 gate pre-activations -> sXG row (stride 49: conflict-free) ----
    {
        float* st = &sXG[tid*49];
        #pragma unroll
        for (int g=0; g<48; g++){
            float acc = sB[g];
            #pragma unroll
            for (int q=0; q<4; q++){
                float4 wvv = sW[g*4 + q];
                acc = fmaf(x[4*q+0], wvv.x, acc);
                acc = fmaf(x[4*q+1], wvv.y, acc);
                acc = fmaf(x[4*q+2], wvv.z, acc);
                acc = fmaf(x[4*q+3], wvv.w, acc);
            }
            st[g] = acc;
        }
    }
    __syncthreads();   // tables dead below; sH aliases them

    // Phase-C weights (loaded during B by idle warps, after B by LSTM warps)
    float wt[5][12], bs[5];

    // ---- Phase B: warps 0/1 run fwd/bwd; warps 2/3 preload C weights ----
    if (warp < 2){
        int d   = warp;
        int jc  = (lane < 24) ? lane : 0;
        bool is_g = (lane >= 12 && lane < 18);
        float sm = is_g ? 1.f : 0.5f;     // sigmoid(x) = 0.5*tanh(0.5x)+0.5
        float ab = is_g ? 0.f : 0.5f;

        const float* Whh = d ? Whh_b : Whh_f;
        float w0=__ldg(Whh+jc*6+0), w1=__ldg(Whh+jc*6+1), w2=__ldg(Whh+jc*6+2),
              w3=__ldg(Whh+jc*6+3), w4=__ldg(Whh+jc*6+4), w5=__ldg(Whh+jc*6+5);

        const float* xgp = &sXG[d*24];
        float h0=0.f,h1=0.f,h2=0.f,h3=0.f,h4=0.f,h5=0.f,c=0.f;
        int s  = d ? (Ssz-1) : 0;
        int ds = d ? -1 : 1;

        float pf = xgp[s*49 + jc];
        #pragma unroll 4
        for (int t=0; t<Ssz; t++){
            float gcur = pf;
            if (t+1 < Ssz) pf = xgp[(s+ds)*49 + jc];   // one-ahead smem prefetch

            float g = fmaf(w0,h0,gcur);
            g = fmaf(w1,h1,g); g = fmaf(w2,h2,g); g = fmaf(w3,h3,g);
            g = fmaf(w4,h4,g); g = fmaf(w5,h5,g);
            float act = fmaf(sm, tanh_fast(g*sm), ab);

            float af = __shfl_sync(FULL, act, lane+6);
            float ag = __shfl_sync(FULL, act, lane+12);
            float ao = __shfl_sync(FULL, act, lane+18);
            c = fmaf(af, c, act*ag);
            float hj = ao * tanh_fast(c);

            h0=__shfl_sync(FULL,hj,0); h1=__shfl_sync(FULL,hj,1); h2=__shfl_sync(FULL,hj,2);
            h3=__shfl_sync(FULL,hj,3); h4=__shfl_sync(FULL,hj,4); h5=__shfl_sync(FULL,hj,5);

            if (lane < 6) sH[s*12 + d*6 + lane] = hj;
            s += ds;
        }
        // LSTM warps load their C weights after the recurrence (overlaps sync wait)
        #pragma unroll
        for (int t5=0; t5<5; t5++){
            int j = lane + 32*t5;
            bool valid = (j < 135);
            bs[t5] = valid ? __ldg(bt + j) : -1e30f;
            #pragma unroll
            for (int k=0;k<12;k++) wt[t5][k] = valid ? __ldg(Wt + j*12 + k) : 0.f;
        }
    } else {
        // idle warps preload C weights during the recurrence window
        #pragma unroll
        for (int t5=0; t5<5; t5++){
            int j = lane + 32*t5;
            bool valid = (j < 135);
            bs[t5] = valid ? __ldg(bt + j) : -1e30f;
            #pragma unroll
            for (int k=0;k<12;k++) wt[t5][k] = valid ? __ldg(Wt + j*12 + k) : 0.f;
        }
    }
    __syncthreads();

    // ---- Phase C: tag linear + log_softmax, weights in registers ----
    int base = warp*32;
    for (int it=0; it<32; it++){
        int p = base + it;
        const float4* hp = (const float4*)(sH + p*12);   // 48B stride, aligned, broadcast
        float4 h0v = hp[0], h1v = hp[1], h2v = hp[2];
        float h[12] = {h0v.x,h0v.y,h0v.z,h0v.w, h1v.x,h1v.y,h1v.z,h1v.w,
                       h2v.x,h2v.y,h2v.z,h2v.w};

        // |v| bounded (|h|<1, small weights): safe to skip max-shift
        float tg[5]; float zs = 0.f;
        #pragma unroll
        for (int t5=0; t5<5; t5++){
            float v = bs[t5];
            #pragma unroll
            for (int k=0;k<12;k++) v = fmaf(h[k], wt[t5][k], v);
            tg[t5] = v;
            zs += __expf(v);
        }
        #pragma unroll
        for (int o=16;o>0;o>>=1) zs += __shfl_xor_sync(FULL, zs, o);
        float lse = __logf(zs);

        float* op = out + ((size_t)blk*Ssz + p)*135;
        #pragma unroll
        for (int t5=0; t5<5; t5++){
            int j = lane + 32*t5;
            if (j < 135) op[j] = tg[t5] - lse;
        }
    }
}

// ---------------- Launch ----------------
extern "C" void kernel_launch(void* const* d_in, const int* in_sizes, int n_in,
                              void* d_out, int out_size)
{
    const int *word_idx=nullptr,*char_idx=nullptr;
    const float *word_emb=nullptr,*char_emb=nullptr,*Wc=nullptr,*bc=nullptr,
        *Wih_f=nullptr,*Whh_f=nullptr,*b_f=nullptr,
        *Wih_b=nullptr,*Whh_b=nullptr,*b_b=nullptr,*Wt=nullptr,*bt=nullptr;
    for (int i=0;i<n_in;i++){
        int sz = in_sizes[i]; const void* p = d_in[i];
        switch (sz){
            case 131072:  word_idx=(const int*)p; break;          // [B,S]
            case 1835008: char_idx=(const int*)p; break;          // [B,S,LP]
            case 500000:  word_emb=(const float*)p; break;        // [V,WE]
            case 600:     char_emb=(const float*)p; break;        // [A,CE]
            case 72:      Wc=(const float*)p; break;              // [Lf,K*CE]
            case 4:       bc=(const float*)p; break;              // [Lf]
            case 336:     if(!Wih_f) Wih_f=(const float*)p; else Wih_b=(const float*)p; break;
            case 144:     if(!Whh_f) Whh_f=(const float*)p; else Whh_b=(const float*)p; break;
            case 24:      if(!b_f)   b_f  =(const float*)p; else b_b  =(const float*)p; break;
            case 1620:    Wt=(const float*)p; break;              // [T,2H]
            case 135:     bt=(const float*)p; break;              // [T]
        }
    }

    fused_tagger<<<Bsz, 128>>>(word_idx, char_idx, word_emb, char_emb,
                               Wc, bc, Wih_f, b_f, Wih_b, b_b,
                               Whh_f, Whh_b, Wt, bt, (float*)d_out);
    (void)out_size; (void)n_in;
}

// round 11
// speedup vs baseline: 1.5877x; 1.1322x over previous
#include <cuda_runtime.h>
#include <cuda_bf16.h>
#include <math_constants.h>

#define Bsz 1024
#define Ssz 128
#define NW (Bsz*Ssz)   // 131072 words

__device__ __forceinline__ float tanh_fast(float x){ float y; asm("tanh.approx.f32 %0, %1;" : "=f"(y) : "f"(x)); return y; }

// ============ fully fused: one block per sentence, 128 threads ============
// Phase A: 128 threads, 1 word each: char-CNN + emb + 48 xgate pre-acts -> sXG
// Phase B: warps 0/1 = fwd/bwd LSTM from sXG -> sH (aliases dead tables);
//          warps 2/3 preload Phase-C weights meanwhile.
// Phase C: 4 warps x 32 pairs (unroll 2 -> overlapped reduction chains)
__global__ __launch_bounds__(128,5) void fused_tagger(
    const int* __restrict__ word_idx, const int* __restrict__ char_idx,
    const float* __restrict__ word_emb, const float* __restrict__ char_emb,
    const float* __restrict__ Wc, const float* __restrict__ bc,
    const float* __restrict__ Wih_f, const float* __restrict__ b_f,
    const float* __restrict__ Wih_b, const float* __restrict__ b_b,
    const float* __restrict__ Whh_f, const float* __restrict__ Whh_b,
    const float* __restrict__ Wt, const float* __restrict__ bt,
    float* __restrict__ out)
{
    // aliased region: tables (Phase A) / sH (Phase B/C)
    __shared__ __align__(16) char uraw[8064];
    float4* sP = (float4*)uraw;                    // 300 entries (4800 B)
    float4* sW = (float4*)(uraw + 4800);           // 192 entries (3072 B)
    float*  sB = (float*)(uraw + 4800 + 3072);     // 48 floats
    float*  sH = (float*)uraw;                     // [128 steps][12] (after Phase A)

    __shared__ float sXG[Ssz*49];  // [word][49]: gates 0..23 fwd, 24..47 bwd, 1 pad

    const unsigned FULL = 0xffffffffu;
    int tid  = threadIdx.x;
    int lane = tid & 31;
    int warp = tid >> 5;
    int blk  = blockIdx.x;         // sentence

    // ---- hoist per-word global loads (latency overlaps table build) ----
    size_t w = (size_t)blk*Ssz + tid;
    int ci[14];
    const int2* cp = (const int2*)(char_idx + w*14);
    #pragma unroll
    for (int k=0;k<7;k++){ int2 v = __ldg(cp+k); ci[2*k]=v.x; ci[2*k+1]=v.y; }

    float x[16];
    int widx = __ldg(word_idx + w);
    const float2* wep = (const float2*)(word_emb) + (size_t)widx*5;
    #pragma unroll
    for (int k=0;k<5;k++){ float2 v = __ldg(wep+k); x[2*k]=v.x; x[2*k+1]=v.y; }
    x[14]=0.f; x[15]=0.f;

    // ---- build tables ----
    for (int i = tid; i < 300; i += 128){
        int c = i/3, k = i%3;
        float4 acc;
        if (k==0){ acc.x=__ldg(bc+0); acc.y=__ldg(bc+1); acc.z=__ldg(bc+2); acc.w=__ldg(bc+3); }
        else     { acc.x=0.f; acc.y=0.f; acc.z=0.f; acc.w=0.f; }
        #pragma unroll
        for (int m=0;m<6;m++){
            float e = __ldg(char_emb + c*6 + m);
            acc.x = fmaf(e, __ldg(Wc + 0*18 + k*6 + m), acc.x);
            acc.y = fmaf(e, __ldg(Wc + 1*18 + k*6 + m), acc.y);
            acc.z = fmaf(e, __ldg(Wc + 2*18 + k*6 + m), acc.z);
            acc.w = fmaf(e, __ldg(Wc + 3*18 + k*6 + m), acc.w);
        }
        sP[i] = acc;
    }
    for (int i = tid; i < 192; i += 128){
        int g = i >> 2, q = i & 3;
        const float* Wih = (g < 24) ? (Wih_f + g*14) : (Wih_b + (g-24)*14);
        int base = q*4;
        float4 wv;
        wv.x = (base+0 < 14) ? __ldg(Wih+base+0) : 0.f;
        wv.y = (base+1 < 14) ? __ldg(Wih+base+1) : 0.f;
        wv.z = (base+2 < 14) ? __ldg(Wih+base+2) : 0.f;
        wv.w = (base+3 < 14) ? __ldg(Wih+base+3) : 0.f;
        sW[i] = wv;
    }
    if (tid < 48) sB[tid] = (tid < 24) ? __ldg(b_f + tid) : __ldg(b_b + tid - 24);
    __syncthreads();

    // ---- Phase A: conv + maxpool ----
    float4 a = make_float4(-CUDART_INF_F,-CUDART_INF_F,-CUDART_INF_F,-CUDART_INF_F);
    #pragma unroll
    for (int win=0; win<12; win++){
        float4 s0 = sP[ci[win]  *3 + 0];
        float4 s1 = sP[ci[win+1]*3 + 1];
        float4 s2 = sP[ci[win+2]*3 + 2];
        a.x = fmaxf(a.x, s0.x + s1.x + s2.x);
        a.y = fmaxf(a.y, s0.y + s1.y + s2.y);
        a.z = fmaxf(a.z, s0.z + s1.z + s2.z);
        a.w = fmaxf(a.w, s0.w + s1.w + s2.w);
    }
    x[10]=a.x; x[11]=a.y; x[12]=a.z; x[13]=a.w;

    // ---- 48 gate pre-activations -> sXG row (stride 49: conflict-free) ----
    {
        float* st = &sXG[tid*49];
        #pragma unroll
        for (int g=0; g<48; g++){
            float acc = sB[g];
            #pragma unroll
            for (int q=0; q<4; q++){
                float4 wvv = sW[g*4 + q];
                acc = fmaf(x[4*q+0], wvv.x, acc);
                acc = fmaf(x[4*q+1], wvv.y, acc);
                acc = fmaf(x[4*q+2], wvv.z, acc);
                acc = fmaf(x[4*q+3], wvv.w, acc);
            }
            st[g] = acc;
        }
    }
    __syncthreads();   // tables dead below; sH aliases them

    // Phase-C weights (loaded during B by idle warps, after B by LSTM warps)
    float wt[5][12], bs[5];

    // ---- Phase B: warps 0/1 run fwd/bwd; warps 2/3 preload C weights ----
    if (warp < 2){
        int d   = warp;
        int jc  = (lane < 24) ? lane : 0;
        bool is_g = (lane >= 12 && lane < 18);
        float sm = is_g ? 1.f : 0.5f;     // sigmoid(x) = 0.5*tanh(0.5x)+0.5
        float ab = is_g ? 0.f : 0.5f;

        const float* Whh = d ? Whh_b : Whh_f;
        float w0=__ldg(Whh+jc*6+0), w1=__ldg(Whh+jc*6+1), w2=__ldg(Whh+jc*6+2),
              w3=__ldg(Whh+jc*6+3), w4=__ldg(Whh+jc*6+4), w5=__ldg(Whh+jc*6+5);

        const float* xgp = &sXG[d*24];
        float h0=0.f,h1=0.f,h2=0.f,h3=0.f,h4=0.f,h5=0.f,c=0.f;
        int s  = d ? (Ssz-1) : 0;
        int ds = d ? -1 : 1;

        float pf = xgp[s*49 + jc];
        #pragma unroll 4
        for (int t=0; t<Ssz; t++){
            float gcur = pf;
            if (t+1 < Ssz) pf = xgp[(s+ds)*49 + jc];   // one-ahead smem prefetch

            float g = fmaf(w0,h0,gcur);
            g = fmaf(w1,h1,g); g = fmaf(w2,h2,g); g = fmaf(w3,h3,g);
            g = fmaf(w4,h4,g); g = fmaf(w5,h5,g);
            float act = fmaf(sm, tanh_fast(g*sm), ab);

            float af = __shfl_sync(FULL, act, lane+6);
            float ag = __shfl_sync(FULL, act, lane+12);
            float ao = __shfl_sync(FULL, act, lane+18);
            c = fmaf(af, c, act*ag);
            float hj = ao * tanh_fast(c);

            h0=__shfl_sync(FULL,hj,0); h1=__shfl_sync(FULL,hj,1); h2=__shfl_sync(FULL,hj,2);
            h3=__shfl_sync(FULL,hj,3); h4=__shfl_sync(FULL,hj,4); h5=__shfl_sync(FULL,hj,5);

            if (lane < 6) sH[s*12 + d*6 + lane] = hj;
            s += ds;
        }
        // LSTM warps load their C weights after the recurrence (overlaps sync wait)
        #pragma unroll
        for (int t5=0; t5<5; t5++){
            int j = lane + 32*t5;
            bool valid = (j < 135);
            bs[t5] = valid ? __ldg(bt + j) : -1e30f;
            #pragma unroll
            for (int k=0;k<12;k++) wt[t5][k] = valid ? __ldg(Wt + j*12 + k) : 0.f;
        }
    } else {
        // idle warps preload C weights during the recurrence window
        #pragma unroll
        for (int t5=0; t5<5; t5++){
            int j = lane + 32*t5;
            bool valid = (j < 135);
            bs[t5] = valid ? __ldg(bt + j) : -1e30f;
            #pragma unroll
            for (int k=0;k<12;k++) wt[t5][k] = valid ? __ldg(Wt + j*12 + k) : 0.f;
        }
    }
    __syncthreads();

    // ---- Phase C: tag linear + log_softmax; unroll 2 overlaps the
    //      independent exp/shfl/log chains of adjacent pairs ----
    int base = warp*32;
    #pragma unroll 2
    for (int it=0; it<32; it++){
        int p = base + it;
        const float4* hp = (const float4*)(sH + p*12);   // 48B stride, aligned, broadcast
        float4 h0v = hp[0], h1v = hp[1], h2v = hp[2];
        float h[12] = {h0v.x,h0v.y,h0v.z,h0v.w, h1v.x,h1v.y,h1v.z,h1v.w,
                       h2v.x,h2v.y,h2v.z,h2v.w};

        // |v| bounded (|h|<1, small weights): safe to skip max-shift
        float tg[5]; float zs = 0.f;
        #pragma unroll
        for (int t5=0; t5<5; t5++){
            float v = bs[t5];
            #pragma unroll
            for (int k=0;k<12;k++) v = fmaf(h[k], wt[t5][k], v);
            tg[t5] = v;
            zs += __expf(v);
        }
        #pragma unroll
        for (int o=16;o>0;o>>=1) zs += __shfl_xor_sync(FULL, zs, o);
        float lse = __logf(zs);

        float* op = out + ((size_t)blk*Ssz + p)*135;
        #pragma unroll
        for (int t5=0; t5<5; t5++){
            int j = lane + 32*t5;
            if (j < 135) op[j] = tg[t5] - lse;
        }
    }
}

// ---------------- Launch ----------------
extern "C" void kernel_launch(void* const* d_in, const int* in_sizes, int n_in,
                              void* d_out, int out_size)
{
    const int *word_idx=nullptr,*char_idx=nullptr;
    const float *word_emb=nullptr,*char_emb=nullptr,*Wc=nullptr,*bc=nullptr,
        *Wih_f=nullptr,*Whh_f=nullptr,*b_f=nullptr,
        *Wih_b=nullptr,*Whh_b=nullptr,*b_b=nullptr,*Wt=nullptr,*bt=nullptr;
    for (int i=0;i<n_in;i++){
        int sz = in_sizes[i]; const void* p = d_in[i];
        switch (sz){
            case 131072:  word_idx=(const int*)p; break;          // [B,S]
            case 1835008: char_idx=(const int*)p; break;          // [B,S,LP]
            case 500000:  word_emb=(const float*)p; break;        // [V,WE]
            case 600:     char_emb=(const float*)p; break;        // [A,CE]
            case 72:      Wc=(const float*)p; break;              // [Lf,K*CE]
            case 4:       bc=(const float*)p; break;              // [Lf]
            case 336:     if(!Wih_f) Wih_f=(const float*)p; else Wih_b=(const float*)p; break;
            case 144:     if(!Whh_f) Whh_f=(const float*)p; else Whh_b=(const float*)p; break;
            case 24:      if(!b_f)   b_f  =(const float*)p; else b_b  =(const float*)p; break;
            case 1620:    Wt=(const float*)p; break;              // [T,2H]
            case 135:     bt=(const float*)p; break;              // [T]
        }
    }

    fused_tagger<<<Bsz, 128>>>(word_idx, char_idx, word_emb, char_emb,
                               Wc, bc, Wih_f, b_f, Wih_b, b_b,
                               Whh_f, Whh_b, Wt, bt, (float*)d_out);
    (void)out_size; (void)n_in;
}